// round 1
// baseline (speedup 1.0000x reference)
#include <cuda_runtime.h>
#include <math.h>

#define Nn 50000
#define Ee 400000
#define Gg 8
#define H  128
#define OUTF 3
#define REPEATS 3

// ---------------- scratch (device globals; no allocation allowed) ----------
__device__ float g_h[Nn * H];
__device__ float g_t[Nn * H];
__device__ float g_P[Nn * H];
__device__ float g_Q[Nn * H];
__device__ float g_R[Nn * H];
__device__ float g_agg[Nn * H];
__device__ float g_cnt[Nn];
__device__ float g_gsum[Gg * H];
__device__ float g_bcsum[Gg * H];
__device__ float g_xg[Gg * H];
__device__ float g_xbc[Gg * H];
__device__ float g_gvec[Gg * H];
__device__ float g_gc[Gg];
__device__ float g_bccnt[Gg];

// ---------------- small utility kernels ------------------------------------
__global__ void zero_groups_kernel(int full) {
    int i = blockIdx.x * 256 + threadIdx.x;   // grid = 4 blocks
    if (i < Gg * H) {
        g_gsum[i] = 0.f;
        if (full) g_bcsum[i] = 0.f;
    }
    if (full && i < Gg) { g_gc[i] = 0.f; g_bccnt[i] = 0.f; }
}

// per-node stats: group counts, bc counts; init cnt[n] = 1 (self loop)
__global__ void node_stats_kernel(const int* __restrict__ batch,
                                  const float* __restrict__ x_mask) {
    __shared__ float sgc[Gg], sbc[Gg];
    int tid = threadIdx.x;
    if (tid < Gg) { sgc[tid] = 0.f; sbc[tid] = 0.f; }
    __syncthreads();
    int n = blockIdx.x * 256 + tid;
    if (n < Nn) {
        int g = batch[n];
        float bc = x_mask[n * 3 + 2];
        atomicAdd(&sgc[g], 1.f);
        atomicAdd(&sbc[g], bc);
        g_cnt[n] = 1.f;
    }
    __syncthreads();
    if (tid < Gg) {
        atomicAdd(&g_gc[tid], sgc[tid]);
        atomicAdd(&g_bccnt[tid], sbc[tid]);
    }
}

__global__ void edge_cnt_kernel(const int* __restrict__ ei) {
    int e = blockIdx.x * 256 + threadIdx.x;
    if (e < Ee) atomicAdd(&g_cnt[ei[Ee + e]], 1.f);
}

// ---------------- encoder layer 1 (K=8, tiny) ------------------------------
__global__ void enc1_kernel(const float* __restrict__ x,
                            const float* __restrict__ xm,
                            const float* __restrict__ W_e1,
                            const float* __restrict__ b_e1) {
    __shared__ float Ws[8 * H];
    __shared__ float bs[H];
    int tid = threadIdx.x;
    for (int i = tid; i < 8 * H; i += 256) Ws[i] = W_e1[i];
    if (tid < H) bs[tid] = b_e1[tid];
    __syncthreads();
    int idx = blockIdx.x * 256 + tid;
    if (idx >= Nn * H) return;
    int n = idx >> 7, j = idx & 127;
    float in8[8];
#pragma unroll
    for (int k = 0; k < 5; k++) in8[k] = x[n * 5 + k];
#pragma unroll
    for (int k = 0; k < 3; k++) in8[5 + k] = xm[n * 3 + k];
    float acc = bs[j];
#pragma unroll
    for (int k = 0; k < 8; k++) acc = fmaf(in8[k], Ws[k * H + j], acc);
    g_t[idx] = fmaxf(acc, 0.f);
}

// ---------------- main node GEMM: C[M x 128] = ep(A @ W) --------------------
// A is [M x K]; element A[m][k] = A0[m*128+k] (k<128) else A1[m*128+(k-128)].
// epilogue: v = acc (/ rowdiv[m]) (+ colbias[j]) (+ rowbias_g[batch[m]*128+j]);
//           relu optional; resid: C += v else C = v.
template <bool RELU, bool RESID>
__global__ __launch_bounds__(256) void gemm_node(
    const float* __restrict__ A0, const float* __restrict__ A1, int K,
    const float* __restrict__ W, const float* __restrict__ colbias,
    const float* __restrict__ rowbias_g, const int* __restrict__ batch,
    const float* __restrict__ rowdiv, float* __restrict__ C, int M) {
    const int BM = 128, BK = 8;
    __shared__ float As[BK][BM];
    __shared__ float Bs[BK][H];
    int tid = threadIdx.x;
    int tx = tid & 15;          // col group (8 cols each)
    int ty = tid >> 4;          // row group (8 rows each)
    int rowBase = blockIdx.x * BM;

    float acc[8][8];
#pragma unroll
    for (int i = 0; i < 8; i++)
#pragma unroll
        for (int j = 0; j < 8; j++) acc[i][j] = 0.f;

    int a_m = tid >> 1;
    int a_k4 = (tid & 1) * 4;
    int b_j = tid & 127;
    int b_k0 = tid >> 7;

    for (int kt = 0; kt < K; kt += BK) {
        // --- load A tile (float4 per thread, transposed into As[k][m]) ---
        float4 av = make_float4(0.f, 0.f, 0.f, 0.f);
        int row = rowBase + a_m;
        int kb = kt + a_k4;
        if (row < M) {
            const float* src = A0;
            int kk = kb;
            if (A1 != nullptr && kb >= 128) { src = A1; kk = kb - 128; }
            av = *(const float4*)&src[row * H + kk];
        }
        As[a_k4 + 0][a_m] = av.x;
        As[a_k4 + 1][a_m] = av.y;
        As[a_k4 + 2][a_m] = av.z;
        As[a_k4 + 3][a_m] = av.w;
        // --- load B tile (coalesced) ---
#pragma unroll
        for (int i = 0; i < 4; i++) {
            int k = b_k0 + 2 * i;
            Bs[k][b_j] = W[(kt + k) * H + b_j];
        }
        __syncthreads();
#pragma unroll
        for (int k = 0; k < BK; k++) {
            float4 a0 = *(const float4*)&As[k][ty * 8];
            float4 a1 = *(const float4*)&As[k][ty * 8 + 4];
            float4 b0 = *(const float4*)&Bs[k][tx * 8];
            float4 b1 = *(const float4*)&Bs[k][tx * 8 + 4];
            float avv[8] = {a0.x, a0.y, a0.z, a0.w, a1.x, a1.y, a1.z, a1.w};
            float bvv[8] = {b0.x, b0.y, b0.z, b0.w, b1.x, b1.y, b1.z, b1.w};
#pragma unroll
            for (int i = 0; i < 8; i++)
#pragma unroll
                for (int j = 0; j < 8; j++)
                    acc[i][j] = fmaf(avv[i], bvv[j], acc[i][j]);
        }
        __syncthreads();
    }

#pragma unroll
    for (int i = 0; i < 8; i++) {
        int row = rowBase + ty * 8 + i;
        if (row >= M) continue;
        float inv = 1.f;
        if (rowdiv) inv = 1.f / rowdiv[row];
        int gb = 0;
        if (rowbias_g) gb = batch[row];
#pragma unroll
        for (int jj = 0; jj < 2; jj++) {
            int col = tx * 8 + jj * 4;
            float4 v = make_float4(acc[i][jj * 4 + 0], acc[i][jj * 4 + 1],
                                   acc[i][jj * 4 + 2], acc[i][jj * 4 + 3]);
            if (rowdiv) { v.x *= inv; v.y *= inv; v.z *= inv; v.w *= inv; }
            if (colbias) {
                float4 cb = *(const float4*)&colbias[col];
                v.x += cb.x; v.y += cb.y; v.z += cb.z; v.w += cb.w;
            }
            if (rowbias_g) {
                float4 rb = *(const float4*)&rowbias_g[gb * H + col];
                v.x += rb.x; v.y += rb.y; v.z += rb.z; v.w += rb.w;
            }
            if (RELU) {
                v.x = fmaxf(v.x, 0.f); v.y = fmaxf(v.y, 0.f);
                v.z = fmaxf(v.z, 0.f); v.w = fmaxf(v.w, 0.f);
            }
            float* cp = &C[row * H + col];
            if (RESID) {
                float4 o = *(const float4*)cp;
                v.x += o.x; v.y += o.y; v.z += o.z; v.w += o.w;
            }
            *(float4*)cp = v;
        }
    }
}

// ---------------- self-loop init: R = relu(P + Q) ---------------------------
__global__ void selfloop_init_kernel() {
    int i = blockIdx.x * 256 + threadIdx.x;   // over Nn*H/4 float4s
    if (i >= Nn * H / 4) return;
    float4 p = *((const float4*)g_P + i);
    float4 q = *((const float4*)g_Q + i);
    float4 r;
    r.x = fmaxf(p.x + q.x, 0.f);
    r.y = fmaxf(p.y + q.y, 0.f);
    r.z = fmaxf(p.z + q.z, 0.f);
    r.w = fmaxf(p.w + q.w, 0.f);
    *((float4*)g_R + i) = r;
}

// ---------------- edge messages: R[dst] += relu(P[src]+Q[dst]+ea@W_ea) ------
__global__ __launch_bounds__(256) void edge_msg_kernel(
    const int* __restrict__ ei, const float* __restrict__ ea,
    const float* __restrict__ W_m1) {
    __shared__ float Wea[3 * H];
    int tid = threadIdx.x;
    for (int i = tid; i < 3 * H; i += 256) Wea[i] = W_m1[256 * H + i];
    __syncthreads();
    int e = blockIdx.x * 8 + (tid >> 5);
    if (e >= Ee) return;
    int lane = tid & 31;
    int src = ei[e];
    int dst = ei[Ee + e];
    float e0 = __ldg(&ea[e * 3 + 0]);
    float e1 = __ldg(&ea[e * 3 + 1]);
    float e2 = __ldg(&ea[e * 3 + 2]);
    int c = lane * 4;
    float4 p = *(const float4*)&g_P[src * H + c];
    float4 q = *(const float4*)&g_Q[dst * H + c];
    float4 w0 = *(const float4*)&Wea[0 * H + c];
    float4 w1 = *(const float4*)&Wea[1 * H + c];
    float4 w2 = *(const float4*)&Wea[2 * H + c];
    float vx = fmaxf(p.x + q.x + e0 * w0.x + e1 * w1.x + e2 * w2.x, 0.f);
    float vy = fmaxf(p.y + q.y + e0 * w0.y + e1 * w1.y + e2 * w2.y, 0.f);
    float vz = fmaxf(p.z + q.z + e0 * w0.z + e1 * w1.z + e2 * w2.z, 0.f);
    float vw = fmaxf(p.w + q.w + e0 * w0.w + e1 * w1.w + e2 * w2.w, 0.f);
    float* rp = &g_R[dst * H + c];
    atomicAdd(rp + 0, vx);
    atomicAdd(rp + 1, vy);
    atomicAdd(rp + 2, vz);
    atomicAdd(rp + 3, vw);
}

// ---------------- per-group segment sums of h (and bc-weighted) -------------
__global__ void group_sum_kernel(const int* __restrict__ batch,
                                 const float* __restrict__ x_mask, int withbc) {
    int j = threadIdx.x;  // 128 threads
    int chunk = (Nn + gridDim.x - 1) / gridDim.x;
    int n0 = blockIdx.x * chunk;
    int n1 = n0 + chunk;
    if (n1 > Nn) n1 = Nn;
    if (n0 >= n1) return;
    float acc = 0.f, accb = 0.f;
    int gcur = batch[n0];
    for (int n = n0; n < n1; n++) {
        int g = batch[n];
        if (g != gcur) {
            atomicAdd(&g_gsum[gcur * H + j], acc);
            if (withbc) atomicAdd(&g_bcsum[gcur * H + j], accb);
            acc = 0.f; accb = 0.f; gcur = g;
        }
        float v = g_h[n * H + j];
        acc += v;
        if (withbc) accb += v * x_mask[n * 3 + 2];
    }
    atomicAdd(&g_gsum[gcur * H + j], acc);
    if (withbc) atomicAdd(&g_bcsum[gcur * H + j], accb);
}

__global__ void finalize_means_kernel(int withbc) {
    int g = blockIdx.x, j = threadIdx.x;
    float c = fmaxf(g_gc[g], 1.f);
    g_xg[g * H + j] = g_gsum[g * H + j] / c;
    if (withbc) {
        float cb = fmaxf(g_bccnt[g], 1.f);
        g_xbc[g * H + j] = g_bcsum[g * H + j] / cb;
    }
}

// gvec[g] = b_u1 + x_graph[g] @ W_u1[256:384] + x_BC[g] @ W_u1[384:512]
__global__ void gvec_kernel(const float* __restrict__ W_u1,
                            const float* __restrict__ b_u1) {
    int g = blockIdx.x, j = threadIdx.x;
    float acc = b_u1[j];
    for (int k = 0; k < H; k++) {
        acc = fmaf(g_xg[g * H + k], W_u1[(256 + k) * H + j], acc);
        acc = fmaf(g_xbc[g * H + k], W_u1[(384 + k) * H + j], acc);
    }
    g_gvec[g * H + j] = acc;
}

// ---------------- decoder layer 2: out = t @ W_d2 + b_d2 (128 -> 3) ---------
__global__ void dec2_kernel(const float* __restrict__ W_d2,
                            const float* __restrict__ b_d2,
                            float* __restrict__ out) {
    int n = blockIdx.x * 8 + (threadIdx.x >> 5);
    if (n >= Nn) return;
    int lane = threadIdx.x & 31;
    float4 t4 = *(const float4*)&g_t[n * H + lane * 4];
    float tv[4] = {t4.x, t4.y, t4.z, t4.w};
    float a0 = 0.f, a1 = 0.f, a2 = 0.f;
#pragma unroll
    for (int r = 0; r < 4; r++) {
        int k = lane * 4 + r;
        a0 = fmaf(tv[r], __ldg(&W_d2[k * 3 + 0]), a0);
        a1 = fmaf(tv[r], __ldg(&W_d2[k * 3 + 1]), a1);
        a2 = fmaf(tv[r], __ldg(&W_d2[k * 3 + 2]), a2);
    }
#pragma unroll
    for (int off = 16; off; off >>= 1) {
        a0 += __shfl_down_sync(0xffffffffu, a0, off);
        a1 += __shfl_down_sync(0xffffffffu, a1, off);
        a2 += __shfl_down_sync(0xffffffffu, a2, off);
    }
    if (lane == 0) {
        out[n * 3 + 0] = a0 + b_d2[0];
        out[n * 3 + 1] = a1 + b_d2[1];
        out[n * 3 + 2] = a2 + b_d2[2];
    }
}

// ---------------- launch -----------------------------------------------------
extern "C" void kernel_launch(void* const* d_in, const int* in_sizes, int n_in,
                              void* d_out, int out_size) {
    const float* x    = (const float*)d_in[0];
    const float* xm   = (const float*)d_in[1];
    const float* ea   = (const float*)d_in[2];
    // d_in[3] = pos (unused by reference)
    const float* W_e1 = (const float*)d_in[4];
    const float* b_e1 = (const float*)d_in[5];
    const float* W_e2 = (const float*)d_in[6];
    const float* b_e2 = (const float*)d_in[7];
    const float* W_m1 = (const float*)d_in[8];
    const float* b_m1 = (const float*)d_in[9];
    const float* W_m2 = (const float*)d_in[10];
    const float* b_m2 = (const float*)d_in[11];
    const float* W_u1 = (const float*)d_in[12];
    const float* b_u1 = (const float*)d_in[13];
    const float* W_u2 = (const float*)d_in[14];
    const float* b_u2 = (const float*)d_in[15];
    const float* W_d1 = (const float*)d_in[16];
    const float* b_d1 = (const float*)d_in[17];
    const float* W_d2 = (const float*)d_in[18];
    const float* b_d2 = (const float*)d_in[19];
    const int*   ei   = (const int*)d_in[20];
    const int*   batch = (const int*)d_in[21];
    float* out = (float*)d_out;

    float *p_h, *p_t, *p_P, *p_Q, *p_R, *p_agg, *p_cnt, *p_gvec;
    cudaGetSymbolAddress((void**)&p_h, g_h);
    cudaGetSymbolAddress((void**)&p_t, g_t);
    cudaGetSymbolAddress((void**)&p_P, g_P);
    cudaGetSymbolAddress((void**)&p_Q, g_Q);
    cudaGetSymbolAddress((void**)&p_R, g_R);
    cudaGetSymbolAddress((void**)&p_agg, g_agg);
    cudaGetSymbolAddress((void**)&p_cnt, g_cnt);
    cudaGetSymbolAddress((void**)&p_gvec, g_gvec);

    const int GB = (Nn + 127) / 128;  // 391 blocks for node GEMMs

    // setup
    zero_groups_kernel<<<4, 256>>>(1);
    node_stats_kernel<<<(Nn + 255) / 256, 256>>>(batch, xm);
    edge_cnt_kernel<<<(Ee + 255) / 256, 256>>>(ei);

    // encoder
    enc1_kernel<<<(Nn * H + 255) / 256, 256>>>(x, xm, W_e1, b_e1);
    gemm_node<false, false><<<GB, 256>>>(p_t, nullptr, 128, W_e2, b_e2,
                                         nullptr, nullptr, nullptr, p_h, Nn);

    // initial group stats (x_graph, x_BC)
    group_sum_kernel<<<512, 128>>>(batch, xm, 1);
    finalize_means_kernel<<<Gg, 128>>>(1);

    for (int r = 0; r < REPEATS; r++) {
        gvec_kernel<<<Gg, 128>>>(W_u1, b_u1);
        // P = h @ W_src + b_m1 ;  Q = h @ W_dst
        gemm_node<false, false><<<GB, 256>>>(p_h, nullptr, 128, W_m1, b_m1,
                                             nullptr, nullptr, nullptr, p_P, Nn);
        gemm_node<false, false><<<GB, 256>>>(p_h, nullptr, 128, W_m1 + 128 * H,
                                             nullptr, nullptr, nullptr, nullptr,
                                             p_Q, Nn);
        // R init with self loops, then edge accumulation
        selfloop_init_kernel<<<(Nn * H / 4 + 255) / 256, 256>>>();
        edge_msg_kernel<<<(Ee + 7) / 8, 256>>>(ei, ea, W_m1);
        // agg = (R @ W_m2) / cnt + b_m2
        gemm_node<false, false><<<GB, 256>>>(p_R, nullptr, 128, W_m2, b_m2,
                                             nullptr, nullptr, p_cnt, p_agg, Nn);
        // t = relu([h|agg] @ W_u1[0:256] + gvec[batch])
        gemm_node<true, false><<<GB, 256>>>(p_h, p_agg, 256, W_u1, nullptr,
                                            p_gvec, batch, nullptr, p_t, Nn);
        // h += t @ W_u2 + b_u2
        gemm_node<false, true><<<GB, 256>>>(p_t, nullptr, 128, W_u2, b_u2,
                                            nullptr, nullptr, nullptr, p_h, Nn);
        if (r < REPEATS - 1) {
            zero_groups_kernel<<<4, 256>>>(0);
            group_sum_kernel<<<512, 128>>>(batch, xm, 0);
            finalize_means_kernel<<<Gg, 128>>>(0);
        }
    }

    // decoder
    gemm_node<true, false><<<GB, 256>>>(p_h, nullptr, 128, W_d1, b_d1, nullptr,
                                        nullptr, nullptr, p_t, Nn);
    dec2_kernel<<<(Nn + 7) / 8, 256>>>(W_d2, b_d2, out);
}

// round 2
// speedup vs baseline: 1.1816x; 1.1816x over previous
#include <cuda_runtime.h>
#include <math.h>

#define Nn 50000
#define Ee 400000
#define Gg 8
#define H  128
#define OUTF 3
#define REPEATS 3

// ---- packed fp32x2 ops (sm_103a full-rate fp32 path) -----------------------
#define FMA_F32X2(acc, a, b) \
    asm("fma.rn.f32x2 %0, %1, %2, %0;" : "+l"(acc) : "l"(a), "l"(b))
#define PACK_F32X2(out, lo, hi) \
    asm("mov.b64 %0, {%1, %2};" : "=l"(out) : "f"(lo), "f"(hi))
#define UNPACK_F32X2(lo, hi, in) \
    asm("mov.b64 {%0, %1}, %2;" : "=f"(lo), "=f"(hi) : "l"(in))

// ---------------- scratch (device globals; no allocation allowed) ----------
__device__ float g_h[Nn * H];
__device__ float g_t[Nn * H];
__device__ float g_P[Nn * H];
__device__ float g_Q[Nn * H];
__device__ float g_R[Nn * H];
__device__ float g_agg[Nn * H];
__device__ float g_cnt[Nn];
__device__ float g_gsum[Gg * H];
__device__ float g_bcsum[Gg * H];
__device__ float g_xg[Gg * H];
__device__ float g_xbc[Gg * H];
__device__ float g_gvec[Gg * H];
__device__ float g_gc[Gg];
__device__ float g_bccnt[Gg];

// ---------------- small utility kernels ------------------------------------
__global__ void zero_groups_kernel(int full) {
    int i = blockIdx.x * 256 + threadIdx.x;
    if (i < Gg * H) {
        g_gsum[i] = 0.f;
        if (full) g_bcsum[i] = 0.f;
    }
    if (full && i < Gg) { g_gc[i] = 0.f; g_bccnt[i] = 0.f; }
}

__global__ void node_stats_kernel(const int* __restrict__ batch,
                                  const float* __restrict__ x_mask) {
    __shared__ float sgc[Gg], sbc[Gg];
    int tid = threadIdx.x;
    if (tid < Gg) { sgc[tid] = 0.f; sbc[tid] = 0.f; }
    __syncthreads();
    int n = blockIdx.x * 256 + tid;
    if (n < Nn) {
        int g = batch[n];
        float bc = x_mask[n * 3 + 2];
        atomicAdd(&sgc[g], 1.f);
        atomicAdd(&sbc[g], bc);
        g_cnt[n] = 1.f;
    }
    __syncthreads();
    if (tid < Gg) {
        atomicAdd(&g_gc[tid], sgc[tid]);
        atomicAdd(&g_bccnt[tid], sbc[tid]);
    }
}

__global__ void edge_cnt_kernel(const int* __restrict__ ei) {
    int e = blockIdx.x * 256 + threadIdx.x;
    if (e < Ee) atomicAdd(&g_cnt[ei[Ee + e]], 1.f);
}

// ---------------- encoder layer 1 (K=8): 4 outputs / thread ------------------
__global__ void enc1_kernel(const float* __restrict__ x,
                            const float* __restrict__ xm,
                            const float* __restrict__ W_e1,
                            const float* __restrict__ b_e1) {
    __shared__ float Ws[8 * H];
    __shared__ float bs[H];
    int tid = threadIdx.x;
    for (int i = tid; i < 8 * H; i += 256) Ws[i] = W_e1[i];
    if (tid < H) bs[tid] = b_e1[tid];
    __syncthreads();
    int idx = blockIdx.x * 256 + tid;         // over Nn*32
    if (idx >= Nn * 32) return;
    int n = idx >> 5, j4 = (idx & 31) * 4;
    float in8[8];
#pragma unroll
    for (int k = 0; k < 5; k++) in8[k] = x[n * 5 + k];
#pragma unroll
    for (int k = 0; k < 3; k++) in8[5 + k] = xm[n * 3 + k];
    float4 acc = *(const float4*)&bs[j4];
#pragma unroll
    for (int k = 0; k < 8; k++) {
        float4 w = *(const float4*)&Ws[k * H + j4];
        acc.x = fmaf(in8[k], w.x, acc.x);
        acc.y = fmaf(in8[k], w.y, acc.y);
        acc.z = fmaf(in8[k], w.z, acc.z);
        acc.w = fmaf(in8[k], w.w, acc.w);
    }
    acc.x = fmaxf(acc.x, 0.f); acc.y = fmaxf(acc.y, 0.f);
    acc.z = fmaxf(acc.z, 0.f); acc.w = fmaxf(acc.w, 0.f);
    *(float4*)&g_t[n * H + j4] = acc;
}

// ---------------- main node GEMM (f32x2, double-buffered) -------------------
// C[M x 128] = ep(A @ W); A[m][k] from A0 (k<128) else A1 (k-128).
template <bool RELU, bool RESID>
__global__ __launch_bounds__(256, 2) void gemm_node(
    const float* __restrict__ A0, const float* __restrict__ A1, int K,
    const float* __restrict__ W, const float* __restrict__ colbias,
    const float* __restrict__ rowbias_g, const int* __restrict__ batch,
    const float* __restrict__ rowdiv, float* __restrict__ C, int M) {
    const int BM = 128, BK = 8, LDS_PAD = 132;
    __shared__ float As[2][BK][LDS_PAD];
    __shared__ float Bs[2][BK][LDS_PAD];
    int tid = threadIdx.x;
    int tx = tid & 15;          // col group (8 cols -> 4 f32x2 pairs)
    int ty = tid >> 4;          // row group (8 rows)
    int rowBase = blockIdx.x * BM;

    unsigned long long acc[8][4];
#pragma unroll
    for (int i = 0; i < 8; i++)
#pragma unroll
        for (int j = 0; j < 4; j++) acc[i][j] = 0ull;

    int a_m = tid >> 1;
    int a_k4 = (tid & 1) * 4;
    int b_j = tid & 127;
    int b_k = tid >> 7;         // 0 or 1

    float4 aval;
    float bval[4];

    // --- prologue: load tile 0 ---
    {
        int row = rowBase + a_m;
        aval = make_float4(0.f, 0.f, 0.f, 0.f);
        if (row < M) {
            const float* s = A0; int kk = a_k4;
            if (A1 != nullptr && a_k4 >= 128) { s = A1; kk = a_k4 - 128; }
            aval = *(const float4*)&s[row * H + kk];
        }
#pragma unroll
        for (int i = 0; i < 4; i++) bval[i] = W[(b_k + 2 * i) * H + b_j];
        As[0][a_k4 + 0][a_m] = aval.x;
        As[0][a_k4 + 1][a_m] = aval.y;
        As[0][a_k4 + 2][a_m] = aval.z;
        As[0][a_k4 + 3][a_m] = aval.w;
#pragma unroll
        for (int i = 0; i < 4; i++) Bs[0][b_k + 2 * i][b_j] = bval[i];
    }
    __syncthreads();

    int nt = K / BK;
    for (int t = 0; t < nt; t++) {
        int cur = t & 1;
        // prefetch next tile into regs
        if (t + 1 < nt) {
            int kt = (t + 1) * BK;
            int row = rowBase + a_m;
            int kb = kt + a_k4;
            aval = make_float4(0.f, 0.f, 0.f, 0.f);
            if (row < M) {
                const float* s = A0; int kk = kb;
                if (A1 != nullptr && kb >= 128) { s = A1; kk = kb - 128; }
                aval = *(const float4*)&s[row * H + kk];
            }
#pragma unroll
            for (int i = 0; i < 4; i++)
                bval[i] = W[(kt + b_k + 2 * i) * H + b_j];
        }
        // compute on cur
#pragma unroll
        for (int k = 0; k < BK; k++) {
            float4 a0 = *(const float4*)&As[cur][k][ty * 8];
            float4 a1 = *(const float4*)&As[cur][k][ty * 8 + 4];
            ulonglong2 b01 = *(const ulonglong2*)&Bs[cur][k][tx * 8];
            ulonglong2 b23 = *(const ulonglong2*)&Bs[cur][k][tx * 8 + 4];
            unsigned long long bp0 = b01.x, bp1 = b01.y, bp2 = b23.x, bp3 = b23.y;
            float av[8] = {a0.x, a0.y, a0.z, a0.w, a1.x, a1.y, a1.z, a1.w};
#pragma unroll
            for (int i = 0; i < 8; i++) {
                unsigned long long ap;
                PACK_F32X2(ap, av[i], av[i]);
                FMA_F32X2(acc[i][0], ap, bp0);
                FMA_F32X2(acc[i][1], ap, bp1);
                FMA_F32X2(acc[i][2], ap, bp2);
                FMA_F32X2(acc[i][3], ap, bp3);
            }
        }
        // stage next tile into the other buffer
        if (t + 1 < nt) {
            int nb = 1 - cur;
            As[nb][a_k4 + 0][a_m] = aval.x;
            As[nb][a_k4 + 1][a_m] = aval.y;
            As[nb][a_k4 + 2][a_m] = aval.z;
            As[nb][a_k4 + 3][a_m] = aval.w;
#pragma unroll
            for (int i = 0; i < 4; i++) Bs[nb][b_k + 2 * i][b_j] = bval[i];
            __syncthreads();
        }
    }

    // --- epilogue ---
#pragma unroll
    for (int i = 0; i < 8; i++) {
        int row = rowBase + ty * 8 + i;
        if (row >= M) continue;
        float vout[8];
#pragma unroll
        for (int jp = 0; jp < 4; jp++) {
            float lo, hi;
            UNPACK_F32X2(lo, hi, acc[i][jp]);
            vout[2 * jp] = lo;
            vout[2 * jp + 1] = hi;
        }
        float inv = 1.f;
        if (rowdiv) inv = 1.f / rowdiv[row];
        int gb = 0;
        if (rowbias_g) gb = batch[row];
#pragma unroll
        for (int jj = 0; jj < 2; jj++) {
            int col = tx * 8 + jj * 4;
            float4 v = make_float4(vout[jj * 4 + 0], vout[jj * 4 + 1],
                                   vout[jj * 4 + 2], vout[jj * 4 + 3]);
            if (rowdiv) { v.x *= inv; v.y *= inv; v.z *= inv; v.w *= inv; }
            if (colbias) {
                float4 cb = *(const float4*)&colbias[col];
                v.x += cb.x; v.y += cb.y; v.z += cb.z; v.w += cb.w;
            }
            if (rowbias_g) {
                float4 rb = *(const float4*)&rowbias_g[gb * H + col];
                v.x += rb.x; v.y += rb.y; v.z += rb.z; v.w += rb.w;
            }
            if (RELU) {
                v.x = fmaxf(v.x, 0.f); v.y = fmaxf(v.y, 0.f);
                v.z = fmaxf(v.z, 0.f); v.w = fmaxf(v.w, 0.f);
            }
            float* cp = &C[row * H + col];
            if (RESID) {
                float4 o = *(const float4*)cp;
                v.x += o.x; v.y += o.y; v.z += o.z; v.w += o.w;
            }
            *(float4*)cp = v;
        }
    }
}

// ---------------- self-loop init: R = relu(P + Q) ---------------------------
__global__ void selfloop_init_kernel() {
    int i = blockIdx.x * 256 + threadIdx.x;
    if (i >= Nn * H / 4) return;
    float4 p = *((const float4*)g_P + i);
    float4 q = *((const float4*)g_Q + i);
    float4 r;
    r.x = fmaxf(p.x + q.x, 0.f);
    r.y = fmaxf(p.y + q.y, 0.f);
    r.z = fmaxf(p.z + q.z, 0.f);
    r.w = fmaxf(p.w + q.w, 0.f);
    *((float4*)g_R + i) = r;
}

// ---------------- edge messages: R[dst] += relu(P[src]+Q[dst]+ea@W_ea) ------
__global__ __launch_bounds__(256) void edge_msg_kernel(
    const int* __restrict__ ei, const float* __restrict__ ea,
    const float* __restrict__ W_m1) {
    __shared__ float Wea[3 * H];
    int tid = threadIdx.x;
    for (int i = tid; i < 3 * H; i += 256) Wea[i] = W_m1[256 * H + i];
    __syncthreads();
    int e = blockIdx.x * 8 + (tid >> 5);
    if (e >= Ee) return;
    int lane = tid & 31;
    int src = ei[e];
    int dst = ei[Ee + e];
    float e0 = __ldg(&ea[e * 3 + 0]);
    float e1 = __ldg(&ea[e * 3 + 1]);
    float e2 = __ldg(&ea[e * 3 + 2]);
    int c = lane * 4;
    float4 p = *(const float4*)&g_P[src * H + c];
    float4 q = *(const float4*)&g_Q[dst * H + c];
    float4 w0 = *(const float4*)&Wea[0 * H + c];
    float4 w1 = *(const float4*)&Wea[1 * H + c];
    float4 w2 = *(const float4*)&Wea[2 * H + c];
    float vx = fmaxf(p.x + q.x + e0 * w0.x + e1 * w1.x + e2 * w2.x, 0.f);
    float vy = fmaxf(p.y + q.y + e0 * w0.y + e1 * w1.y + e2 * w2.y, 0.f);
    float vz = fmaxf(p.z + q.z + e0 * w0.z + e1 * w1.z + e2 * w2.z, 0.f);
    float vw = fmaxf(p.w + q.w + e0 * w0.w + e1 * w1.w + e2 * w2.w, 0.f);
    float* rp = &g_R[dst * H + c];
    asm volatile("red.global.add.v4.f32 [%0], {%1, %2, %3, %4};"
                 :: "l"(rp), "f"(vx), "f"(vy), "f"(vz), "f"(vw)
                 : "memory");
}

// ---------------- per-group segment sums of h (and bc-weighted) -------------
__global__ void group_sum_kernel(const int* __restrict__ batch,
                                 const float* __restrict__ x_mask, int withbc) {
    int j = threadIdx.x;  // 128 threads
    int chunk = (Nn + gridDim.x - 1) / gridDim.x;
    int n0 = blockIdx.x * chunk;
    int n1 = n0 + chunk;
    if (n1 > Nn) n1 = Nn;
    if (n0 >= n1) return;
    float acc = 0.f, accb = 0.f;
    int gcur = batch[n0];
    for (int n = n0; n < n1; n++) {
        int g = batch[n];
        if (g != gcur) {
            atomicAdd(&g_gsum[gcur * H + j], acc);
            if (withbc) atomicAdd(&g_bcsum[gcur * H + j], accb);
            acc = 0.f; accb = 0.f; gcur = g;
        }
        float v = g_h[n * H + j];
        acc += v;
        if (withbc) accb += v * x_mask[n * 3 + 2];
    }
    atomicAdd(&g_gsum[gcur * H + j], acc);
    if (withbc) atomicAdd(&g_bcsum[gcur * H + j], accb);
}

__global__ void finalize_means_kernel(int withbc) {
    int g = blockIdx.x, j = threadIdx.x;
    float c = fmaxf(g_gc[g], 1.f);
    g_xg[g * H + j] = g_gsum[g * H + j] / c;
    if (withbc) {
        float cb = fmaxf(g_bccnt[g], 1.f);
        g_xbc[g * H + j] = g_bcsum[g * H + j] / cb;
    }
}

// gvec[g] = b_u1 + x_graph[g] @ W_u1[256:384] + x_BC[g] @ W_u1[384:512]
__global__ void gvec_kernel(const float* __restrict__ W_u1,
                            const float* __restrict__ b_u1) {
    int g = blockIdx.x, j = threadIdx.x;
    float acc = b_u1[j];
    for (int k = 0; k < H; k++) {
        acc = fmaf(g_xg[g * H + k], W_u1[(256 + k) * H + j], acc);
        acc = fmaf(g_xbc[g * H + k], W_u1[(384 + k) * H + j], acc);
    }
    g_gvec[g * H + j] = acc;
}

// ---------------- decoder layer 2: out = t @ W_d2 + b_d2 (128 -> 3) ---------
__global__ void dec2_kernel(const float* __restrict__ W_d2,
                            const float* __restrict__ b_d2,
                            float* __restrict__ out) {
    int n = blockIdx.x * 8 + (threadIdx.x >> 5);
    if (n >= Nn) return;
    int lane = threadIdx.x & 31;
    float4 t4 = *(const float4*)&g_t[n * H + lane * 4];
    float tv[4] = {t4.x, t4.y, t4.z, t4.w};
    float a0 = 0.f, a1 = 0.f, a2 = 0.f;
#pragma unroll
    for (int r = 0; r < 4; r++) {
        int k = lane * 4 + r;
        a0 = fmaf(tv[r], __ldg(&W_d2[k * 3 + 0]), a0);
        a1 = fmaf(tv[r], __ldg(&W_d2[k * 3 + 1]), a1);
        a2 = fmaf(tv[r], __ldg(&W_d2[k * 3 + 2]), a2);
    }
#pragma unroll
    for (int off = 16; off; off >>= 1) {
        a0 += __shfl_down_sync(0xffffffffu, a0, off);
        a1 += __shfl_down_sync(0xffffffffu, a1, off);
        a2 += __shfl_down_sync(0xffffffffu, a2, off);
    }
    if (lane == 0) {
        out[n * 3 + 0] = a0 + b_d2[0];
        out[n * 3 + 1] = a1 + b_d2[1];
        out[n * 3 + 2] = a2 + b_d2[2];
    }
}

// ---------------- launch -----------------------------------------------------
extern "C" void kernel_launch(void* const* d_in, const int* in_sizes, int n_in,
                              void* d_out, int out_size) {
    const float* x    = (const float*)d_in[0];
    const float* xm   = (const float*)d_in[1];
    const float* ea   = (const float*)d_in[2];
    // d_in[3] = pos (unused by reference)
    const float* W_e1 = (const float*)d_in[4];
    const float* b_e1 = (const float*)d_in[5];
    const float* W_e2 = (const float*)d_in[6];
    const float* b_e2 = (const float*)d_in[7];
    const float* W_m1 = (const float*)d_in[8];
    const float* b_m1 = (const float*)d_in[9];
    const float* W_m2 = (const float*)d_in[10];
    const float* b_m2 = (const float*)d_in[11];
    const float* W_u1 = (const float*)d_in[12];
    const float* b_u1 = (const float*)d_in[13];
    const float* W_u2 = (const float*)d_in[14];
    const float* b_u2 = (const float*)d_in[15];
    const float* W_d1 = (const float*)d_in[16];
    const float* b_d1 = (const float*)d_in[17];
    const float* W_d2 = (const float*)d_in[18];
    const float* b_d2 = (const float*)d_in[19];
    const int*   ei   = (const int*)d_in[20];
    const int*   batch = (const int*)d_in[21];
    float* out = (float*)d_out;

    float *p_h, *p_t, *p_P, *p_Q, *p_R, *p_agg, *p_cnt, *p_gvec;
    cudaGetSymbolAddress((void**)&p_h, g_h);
    cudaGetSymbolAddress((void**)&p_t, g_t);
    cudaGetSymbolAddress((void**)&p_P, g_P);
    cudaGetSymbolAddress((void**)&p_Q, g_Q);
    cudaGetSymbolAddress((void**)&p_R, g_R);
    cudaGetSymbolAddress((void**)&p_agg, g_agg);
    cudaGetSymbolAddress((void**)&p_cnt, g_cnt);
    cudaGetSymbolAddress((void**)&p_gvec, g_gvec);

    const int GB = (Nn + 127) / 128;  // 391 blocks for node GEMMs

    // setup
    zero_groups_kernel<<<4, 256>>>(1);
    node_stats_kernel<<<(Nn + 255) / 256, 256>>>(batch, xm);
    edge_cnt_kernel<<<(Ee + 255) / 256, 256>>>(ei);

    // encoder
    enc1_kernel<<<(Nn * 32 + 255) / 256, 256>>>(x, xm, W_e1, b_e1);
    gemm_node<false, false><<<GB, 256>>>(p_t, nullptr, 128, W_e2, b_e2,
                                         nullptr, nullptr, nullptr, p_h, Nn);

    // initial group stats (x_graph, x_BC)
    group_sum_kernel<<<512, 128>>>(batch, xm, 1);
    finalize_means_kernel<<<Gg, 128>>>(1);

    for (int r = 0; r < REPEATS; r++) {
        gvec_kernel<<<Gg, 128>>>(W_u1, b_u1);
        // P = h @ W_src + b_m1 ;  Q = h @ W_dst
        gemm_node<false, false><<<GB, 256>>>(p_h, nullptr, 128, W_m1, b_m1,
                                             nullptr, nullptr, nullptr, p_P, Nn);
        gemm_node<false, false><<<GB, 256>>>(p_h, nullptr, 128, W_m1 + 128 * H,
                                             nullptr, nullptr, nullptr, nullptr,
                                             p_Q, Nn);
        // R init with self loops, then edge accumulation
        selfloop_init_kernel<<<(Nn * H / 4 + 255) / 256, 256>>>();
        edge_msg_kernel<<<(Ee + 7) / 8, 256>>>(ei, ea, W_m1);
        // agg = (R @ W_m2) / cnt + b_m2
        gemm_node<false, false><<<GB, 256>>>(p_R, nullptr, 128, W_m2, b_m2,
                                             nullptr, nullptr, p_cnt, p_agg, Nn);
        // t = relu([h|agg] @ W_u1[0:256] + gvec[batch])
        gemm_node<true, false><<<GB, 256>>>(p_h, p_agg, 256, W_u1, nullptr,
                                            p_gvec, batch, nullptr, p_t, Nn);
        // h += t @ W_u2 + b_u2
        gemm_node<false, true><<<GB, 256>>>(p_t, nullptr, 128, W_u2, b_u2,
                                            nullptr, nullptr, nullptr, p_h, Nn);
        if (r < REPEATS - 1) {
            zero_groups_kernel<<<4, 256>>>(0);
            group_sum_kernel<<<512, 128>>>(batch, xm, 0);
            finalize_means_kernel<<<Gg, 128>>>(0);
        }
    }

    // decoder
    gemm_node<true, false><<<GB, 256>>>(p_h, nullptr, 128, W_d1, b_d1, nullptr,
                                        nullptr, nullptr, p_t, Nn);
    dec2_kernel<<<(Nn + 7) / 8, 256>>>(W_d2, b_d2, out);
}